// round 4
// baseline (speedup 1.0000x reference)
#include <cuda_runtime.h>
#include <cstdint>

#define BATCH   16
#define H       128
#define W       128
#define NC      80
#define ROWLEN  (W * NC)        // 10240
#define BATCHLEN (H * ROWLEN)   // 1310720
#define TOPK    100

// Scratch (device globals: allocation-free contract)
__device__ unsigned long long g_cand[BATCH][BATCHLEN];
__device__ unsigned int g_cnt[BATCH];

__global__ void zero_kernel() {
    if (threadIdx.x < BATCH) g_cnt[threadIdx.x] = 0u;
}

__device__ __forceinline__ float4 maxf4(float4 a, float4 b) {
    return make_float4(fmaxf(a.x, b.x), fmaxf(a.y, b.y),
                       fmaxf(a.z, b.z), fmaxf(a.w, b.w));
}

#define SBUF_CAP   5120   // 4096 flush threshold + 1024 max per iteration
#define SBUF_FLUSH 4096
#define YSTRIP     32

// Peak-NMS kernel: logit-domain 3x3 max via separable (horizontal then vertical
// sliding window). Each thread owns one float4 column (4 classes at one x),
// iterates 32+2 rows. Peaks -> warp-aggregated append to smem, bulk flush.
__global__ __launch_bounds__(256) void peak_kernel(const float* __restrict__ cls) {
    __shared__ unsigned long long sbuf[SBUF_CAP];
    __shared__ unsigned int scnt;
    __shared__ unsigned int sbase;

    const int tid = threadIdx.x;
    if (tid == 0) scnt = 0u;
    __syncthreads();

    const int b  = blockIdx.z;
    const int ys = blockIdx.y;
    const int jt = blockIdx.x;
    const int j  = jt * 1024 + tid * 4;      // column group within row (w*nc)
    const int xc = j / NC;                    // x coordinate (all 4 lanes same x)
    const bool hasL = (xc > 0);
    const bool hasR = (xc < W - 1);

    const float* base = cls + (size_t)b * BATCHLEN;
    const float NEG = __int_as_float(0xff800000);  // -inf
    const float4 NEG4 = make_float4(NEG, NEG, NEG, NEG);

    const int y0 = ys * YSTRIP;

    float4 hprev, hcur, vcur;
    // h(y0-1)
    if (y0 - 1 < 0) {
        hprev = NEG4;
    } else {
        const float* r = base + (y0 - 1) * ROWLEN + j;
        float4 Bv = *reinterpret_cast<const float4*>(r);
        float4 A = hasL ? *reinterpret_cast<const float4*>(r - NC) : NEG4;
        float4 C = hasR ? *reinterpret_cast<const float4*>(r + NC) : NEG4;
        hprev = maxf4(maxf4(A, Bv), C);
    }
    // h(y0), v(y0)
    {
        const float* r = base + y0 * ROWLEN + j;
        float4 Bv = *reinterpret_cast<const float4*>(r);
        float4 A = hasL ? *reinterpret_cast<const float4*>(r - NC) : NEG4;
        float4 C = hasR ? *reinterpret_cast<const float4*>(r + NC) : NEG4;
        vcur = Bv;
        hcur = maxf4(maxf4(A, Bv), C);
    }

    const unsigned lane = tid & 31u;
    const unsigned lane_lt = (1u << lane) - 1u;

    for (int y = y0; y < y0 + YSTRIP; ++y) {
        float4 vnext, hnext;
        const int yn = y + 1;
        if (yn >= H) {
            vnext = NEG4; hnext = NEG4;
        } else {
            const float* r = base + yn * ROWLEN + j;
            float4 Bv = *reinterpret_cast<const float4*>(r);
            float4 A = hasL ? *reinterpret_cast<const float4*>(r - NC) : NEG4;
            float4 C = hasR ? *reinterpret_cast<const float4*>(r + NC) : NEG4;
            vnext = Bv;
            hnext = maxf4(maxf4(A, Bv), C);
        }

        float4 m = maxf4(maxf4(hprev, hcur), hnext);
        float vv[4] = {vcur.x, vcur.y, vcur.z, vcur.w};
        float mm[4] = {m.x, m.y, m.z, m.w};

        #pragma unroll
        for (int t = 0; t < 4; ++t) {
            bool pk = (vv[t] == mm[t]);
            unsigned ball = __ballot_sync(0xffffffffu, pk);
            if (ball) {
                int leader = __ffs(ball) - 1;
                unsigned pos = 0;
                if ((int)lane == leader)
                    pos = atomicAdd(&scnt, (unsigned)__popc(ball));
                pos = __shfl_sync(0xffffffffu, pos, leader);
                if (pk) {
                    float p = 1.0f / (1.0f + __expf(-vv[t]));
                    unsigned idx = (unsigned)(y * ROWLEN + j + t);
                    unsigned off = pos + (unsigned)__popc(ball & lane_lt);
                    if (off < SBUF_CAP)
                        sbuf[off] = ((unsigned long long)__float_as_uint(p) << 32)
                                  | (unsigned long long)(0xFFFFFFFFu - idx);
                }
            }
        }

        hprev = hcur; hcur = hnext; vcur = vnext;

        __syncthreads();
        if (scnt >= SBUF_FLUSH) {
            unsigned n = scnt; if (n > SBUF_CAP) n = SBUF_CAP;
            if (tid == 0) sbase = atomicAdd(&g_cnt[b], n);
            __syncthreads();
            unsigned sb = sbase;
            for (unsigned i = tid; i < n; i += 256u)
                g_cand[b][sb + i] = sbuf[i];
            __syncthreads();
            if (tid == 0) scnt = 0u;
            __syncthreads();
        }
    }

    // final flush
    {
        unsigned n = scnt; if (n > SBUF_CAP) n = SBUF_CAP;
        if (n) {
            if (tid == 0) sbase = atomicAdd(&g_cnt[b], n);
            __syncthreads();
            unsigned sb = sbase;
            for (unsigned i = tid; i < n; i += 256u)
                g_cand[b][sb + i] = sbuf[i];
        }
    }
}

// Per-batch exact top-K: radix select on p_bits (high 32 of key) via 3 histogram
// passes (11/11/10 bits), collect >= T, bitonic sort full 64-bit keys
// (tie -> lower flat index, matching jax top_k), then emit outputs.
__global__ __launch_bounds__(1024) void topk_kernel(const float* __restrict__ dxy,
                                                    const float* __restrict__ swh,
                                                    float* __restrict__ out) {
    const int b = blockIdx.x;
    const int tid = threadIdx.x;
    const int bd = blockDim.x;

    __shared__ unsigned int hist[2048];
    __shared__ unsigned long long list[4096];
    __shared__ unsigned int sh_prefix;
    __shared__ int sh_rem;
    __shared__ unsigned int lcnt;

    unsigned N = g_cnt[b];
    if (N > (unsigned)BATCHLEN) N = BATCHLEN;
    const unsigned long long* cand = g_cand[b];

    unsigned prefix = 0u;
    int remaining = TOPK;

    if (N > (unsigned)TOPK) {
        const int shifts[3] = {21, 10, 0};
        const int nbits[3]  = {11, 11, 10};
        for (int ps = 0; ps < 3; ++ps) {
            const int shift = shifts[ps];
            const unsigned mask = (1u << nbits[ps]) - 1u;
            const int hs = shift + nbits[ps];
            for (int i = tid; i < 2048; i += bd) hist[i] = 0u;
            __syncthreads();
            for (unsigned i = tid; i < N; i += bd) {
                unsigned v = (unsigned)(cand[i] >> 32);
                bool ok = (ps == 0) || ((v >> hs) == (prefix >> hs));
                if (ok) atomicAdd(&hist[(v >> shift) & mask], 1u);
            }
            __syncthreads();
            if (tid == 0) {
                unsigned cum = 0u;
                int bsel = 0;
                for (int i = (int)mask; i >= 0; --i) {
                    unsigned hv = hist[i];
                    if (cum + hv >= (unsigned)remaining) { bsel = i; break; }
                    cum += hv;
                }
                sh_prefix = prefix | ((unsigned)bsel << shift);
                sh_rem = remaining - (int)cum;
            }
            __syncthreads();
            prefix = sh_prefix;
            remaining = sh_rem;
            __syncthreads();
        }
    }

    const unsigned T = (N > (unsigned)TOPK) ? prefix : 0u;

    if (tid == 0) lcnt = 0u;
    __syncthreads();
    for (unsigned i = tid; i < N; i += bd) {
        unsigned long long key = cand[i];
        if ((unsigned)(key >> 32) >= T) {
            unsigned p2 = atomicAdd(&lcnt, 1u);
            if (p2 < 4096u) list[p2] = key;
        }
    }
    __syncthreads();

    unsigned M = lcnt; if (M > 4096u) M = 4096u;
    unsigned P = 128u;
    while (P < M) P <<= 1;
    for (unsigned i = M + tid; i < P; i += bd) list[i] = 0ull;
    __syncthreads();

    // bitonic sort, descending
    for (unsigned k = 2u; k <= P; k <<= 1) {
        for (unsigned jj = k >> 1; jj > 0u; jj >>= 1) {
            for (unsigned i = tid; i < P; i += bd) {
                unsigned ixj = i ^ jj;
                if (ixj > i) {
                    unsigned long long a = list[i];
                    unsigned long long c = list[ixj];
                    bool up = ((i & k) == 0u);
                    bool sw = up ? (a < c) : (a > c);
                    if (sw) { list[i] = c; list[ixj] = a; }
                }
            }
            __syncthreads();
        }
    }

    if (tid < TOPK) {
        unsigned long long key = list[tid];
        float p = __uint_as_float((unsigned)(key >> 32));
        unsigned idx = 0xFFFFFFFFu - (unsigned)(key & 0xFFFFFFFFull);
        if (idx >= (unsigned)BATCHLEN) idx = 0u;   // safety (only possible on padded keys)
        unsigned c = idx % NC;
        unsigned s = idx / NC;
        unsigned xg = s % W;
        unsigned yg = s / W;
        size_t gi = ((size_t)b * (H * W) + s) * 2;
        float dx = dxy[gi],  dy = dxy[gi + 1];
        float sw = swh[gi],  sh = swh[gi + 1];
        float xs = (float)xg + dx;
        float ysv = (float)yg + dy;
        float hw = sw * 0.5f;
        float hh = sh * 0.5f;
        const float invW = 1.0f / (float)W;
        const float invH = 1.0f / (float)H;
        float x1 = (xs - hw) * invW;
        float y1 = (ysv - hh) * invH;
        float x2 = (xs + hw) * invW;
        float y2 = (ysv + hh) * invH;

        int ok = b * TOPK + tid;
        out[ok * 4 + 0] = x1;
        out[ok * 4 + 1] = y1;
        out[ok * 4 + 2] = x2;
        out[ok * 4 + 3] = y2;
        out[BATCH * TOPK * 4 + ok] = p;                 // confi
        out[BATCH * TOPK * 4 + BATCH * TOPK + ok] = (float)c;  // classes
    }
}

extern "C" void kernel_launch(void* const* d_in, const int* in_sizes, int n_in,
                              void* d_out, int out_size) {
    const float* cls = (const float*)d_in[0];
    const float* dxy = (const float*)d_in[1];
    const float* swh = (const float*)d_in[2];
    float* out = (float*)d_out;

    zero_kernel<<<1, 32>>>();
    peak_kernel<<<dim3(ROWLEN / 1024, H / YSTRIP, BATCH), 256>>>(cls);
    topk_kernel<<<BATCH, 1024>>>(dxy, swh, out);
}

// round 5
// speedup vs baseline: 1.9206x; 1.9206x over previous
#include <cuda_runtime.h>
#include <cstdint>

#define BATCH   16
#define H       128
#define W       128
#define NC      80
#define ROWLEN  (W * NC)        // 10240
#define BATCHLEN (H * ROWLEN)   // 1310720
#define TOPK    100
#define NBINS   2048

// Scratch (device globals: allocation-free contract)
__device__ unsigned long long g_cand[BATCH][BATCHLEN];
__device__ unsigned int g_cnt[BATCH];
__device__ unsigned int g_hist[BATCH][NBINS];

// Identical sigmoid in both kernels (monotone: MUFU.EX2 + reciprocal are
// faithfully rounded and monotone), so logit >= L0  ==>  p >= sigmoid(L0).
__device__ __forceinline__ float sigmoidf_(float x) {
    return 1.0f / (1.0f + __expf(-x));
}

__global__ void zero_kernel() {
    unsigned i = blockIdx.x * blockDim.x + threadIdx.x;
    // zero 16*2048 hist bins + 16 counters
    for (unsigned k = i; k < BATCH * NBINS; k += gridDim.x * blockDim.x)
        ((unsigned*)g_hist)[k] = 0u;
    if (i < BATCH) g_cnt[i] = 0u;
}

__device__ __forceinline__ float4 maxf4(float4 a, float4 b) {
    return make_float4(fmaxf(a.x, b.x), fmaxf(a.y, b.y),
                       fmaxf(a.z, b.z), fmaxf(a.w, b.w));
}

#define SBUF_CAP   5120
#define SBUF_FLUSH 4096
#define YSTRIP     32

// Peak-NMS: logit-domain separable 3x3 max. Peaks append (p<<32|~idx) keys via
// warp-aggregated smem staging, and bump the per-batch 2048-bin histogram of
// sortable-logit high bits via red.global (no-return, spread addresses).
__global__ __launch_bounds__(256) void peak_kernel(const float* __restrict__ cls) {
    __shared__ unsigned long long sbuf[SBUF_CAP];
    __shared__ unsigned int scnt;
    __shared__ unsigned int sbase;

    const int tid = threadIdx.x;
    if (tid == 0) scnt = 0u;
    __syncthreads();

    const int b  = blockIdx.z;
    const int ys = blockIdx.y;
    const int jt = blockIdx.x;
    const int j  = jt * 1024 + tid * 4;      // column group within row (w*nc)
    const int xc = j / NC;                    // x coordinate (4 lanes share x)
    const bool hasL = (xc > 0);
    const bool hasR = (xc < W - 1);

    const float* base = cls + (size_t)b * BATCHLEN;
    const float NEG = __int_as_float(0xff800000);  // -inf
    const float4 NEG4 = make_float4(NEG, NEG, NEG, NEG);

    const int y0 = ys * YSTRIP;

    float4 hprev, hcur, vcur;
    if (y0 - 1 < 0) {
        hprev = NEG4;
    } else {
        const float* r = base + (y0 - 1) * ROWLEN + j;
        float4 Bv = *reinterpret_cast<const float4*>(r);
        float4 A = hasL ? *reinterpret_cast<const float4*>(r - NC) : NEG4;
        float4 C = hasR ? *reinterpret_cast<const float4*>(r + NC) : NEG4;
        hprev = maxf4(maxf4(A, Bv), C);
    }
    {
        const float* r = base + y0 * ROWLEN + j;
        float4 Bv = *reinterpret_cast<const float4*>(r);
        float4 A = hasL ? *reinterpret_cast<const float4*>(r - NC) : NEG4;
        float4 C = hasR ? *reinterpret_cast<const float4*>(r + NC) : NEG4;
        vcur = Bv;
        hcur = maxf4(maxf4(A, Bv), C);
    }

    const unsigned lane = tid & 31u;
    const unsigned lane_lt = (1u << lane) - 1u;

    for (int y = y0; y < y0 + YSTRIP; ++y) {
        float4 vnext, hnext;
        const int yn = y + 1;
        if (yn >= H) {
            vnext = NEG4; hnext = NEG4;
        } else {
            const float* r = base + yn * ROWLEN + j;
            float4 Bv = *reinterpret_cast<const float4*>(r);
            float4 A = hasL ? *reinterpret_cast<const float4*>(r - NC) : NEG4;
            float4 C = hasR ? *reinterpret_cast<const float4*>(r + NC) : NEG4;
            vnext = Bv;
            hnext = maxf4(maxf4(A, Bv), C);
        }

        float4 m = maxf4(maxf4(hprev, hcur), hnext);
        float vv[4] = {vcur.x, vcur.y, vcur.z, vcur.w};
        float mm[4] = {m.x, m.y, m.z, m.w};

        #pragma unroll
        for (int t = 0; t < 4; ++t) {
            bool pk = (vv[t] == mm[t]);
            unsigned ball = __ballot_sync(0xffffffffu, pk);
            if (ball) {
                int leader = __ffs(ball) - 1;
                unsigned pos = 0;
                if ((int)lane == leader)
                    pos = atomicAdd(&scnt, (unsigned)__popc(ball));
                pos = __shfl_sync(0xffffffffu, pos, leader);
                if (pk) {
                    float v = vv[t];
                    // histogram on sortable-logit high 11 bits
                    unsigned u = __float_as_uint(v);
                    unsigned srt = ((int)u < 0) ? ~u : (u | 0x80000000u);
                    atomicAdd(&g_hist[b][srt >> 21], 1u);   // -> RED.GLOBAL
                    float p = sigmoidf_(v);
                    unsigned idx = (unsigned)(y * ROWLEN + j + t);
                    unsigned off = pos + (unsigned)__popc(ball & lane_lt);
                    if (off < SBUF_CAP)
                        sbuf[off] = ((unsigned long long)__float_as_uint(p) << 32)
                                  | (unsigned long long)(0xFFFFFFFFu - idx);
                }
            }
        }

        hprev = hcur; hcur = hnext; vcur = vnext;

        __syncthreads();
        if (scnt >= SBUF_FLUSH) {
            unsigned n = scnt; if (n > SBUF_CAP) n = SBUF_CAP;
            if (tid == 0) sbase = atomicAdd(&g_cnt[b], n);
            __syncthreads();
            unsigned sb = sbase;
            for (unsigned i = tid; i < n; i += 256u)
                g_cand[b][sb + i] = sbuf[i];
            __syncthreads();
            if (tid == 0) scnt = 0u;
            __syncthreads();
        }
    }

    {
        unsigned n = scnt; if (n > SBUF_CAP) n = SBUF_CAP;
        if (n) {
            if (tid == 0) sbase = atomicAdd(&g_cnt[b], n);
            __syncthreads();
            unsigned sb = sbase;
            for (unsigned i = tid; i < n; i += 256u)
                g_cand[b][sb + i] = sbuf[i];
        }
    }
}

// Per-batch final: histogram walk -> p-domain threshold -> single collect scan
// -> bitonic sort of the (p_bits<<32 | ~idx) keys (exact jax tie semantics) -> emit.
__global__ __launch_bounds__(1024) void final_kernel(const float* __restrict__ dxy,
                                                     const float* __restrict__ swh,
                                                     float* __restrict__ out) {
    const int b = blockIdx.x;
    const int tid = threadIdx.x;
    const int bd = blockDim.x;

    __shared__ unsigned int shist[NBINS];
    __shared__ unsigned long long list[4096];
    __shared__ unsigned int sh_thr;
    __shared__ unsigned int lcnt;

    unsigned N = g_cnt[b];
    if (N > (unsigned)BATCHLEN) N = BATCHLEN;
    const unsigned long long* cand = g_cand[b];

    for (int i = tid; i < NBINS; i += bd) shist[i] = g_hist[b][i];
    if (tid == 0) lcnt = 0u;
    __syncthreads();

    if (tid == 0) {
        unsigned thr = 0u;
        if (N > (unsigned)TOPK) {
            unsigned cum = 0u; int bt = 0;
            for (int i = NBINS - 1; i >= 0; --i) {
                cum += shist[i];
                if (cum >= (unsigned)TOPK) { bt = i; break; }
            }
            // bucket lower bound in logit domain (inverse sortable transform)
            unsigned s = (unsigned)bt << 21;
            unsigned bits = (s & 0x80000000u) ? (s ^ 0x80000000u) : ~s;
            float L0 = __uint_as_float(bits);
            // p-domain threshold: identical sigmoid => no tie straddling
            thr = __float_as_uint(sigmoidf_(L0));
        }
        sh_thr = thr;
    }
    __syncthreads();
    const unsigned T = sh_thr;

    // single collect scan (the only full pass over the candidate list here)
    for (unsigned i = tid; i < N; i += bd) {
        unsigned long long key = cand[i];
        if ((unsigned)(key >> 32) >= T) {
            unsigned p2 = atomicAdd(&lcnt, 1u);
            if (p2 < 4096u) list[p2] = key;
        }
    }
    __syncthreads();

    unsigned M = lcnt; if (M > 4096u) M = 4096u;
    unsigned P = 128u;
    while (P < M) P <<= 1;
    for (unsigned i = M + tid; i < P; i += bd) list[i] = 0ull;
    __syncthreads();

    // bitonic sort, descending (full 64-bit key: p desc, index asc on ties)
    for (unsigned k = 2u; k <= P; k <<= 1) {
        for (unsigned jj = k >> 1; jj > 0u; jj >>= 1) {
            for (unsigned i = tid; i < P; i += bd) {
                unsigned ixj = i ^ jj;
                if (ixj > i) {
                    unsigned long long a = list[i];
                    unsigned long long c = list[ixj];
                    bool up = ((i & k) == 0u);
                    bool sw = up ? (a < c) : (a > c);
                    if (sw) { list[i] = c; list[ixj] = a; }
                }
            }
            __syncthreads();
        }
    }

    if (tid < TOPK) {
        unsigned long long key = list[tid];
        float p = __uint_as_float((unsigned)(key >> 32));
        unsigned idx = 0xFFFFFFFFu - (unsigned)(key & 0xFFFFFFFFull);
        if (idx >= (unsigned)BATCHLEN) idx = 0u;   // only reachable via pad keys
        unsigned c = idx % NC;
        unsigned s = idx / NC;
        unsigned xg = s % W;
        unsigned yg = s / W;
        size_t gi = ((size_t)b * (H * W) + s) * 2;
        float dx = dxy[gi],  dy = dxy[gi + 1];
        float sw = swh[gi],  sh = swh[gi + 1];
        float xs = (float)xg + dx;
        float ysv = (float)yg + dy;
        float hw = sw * 0.5f;
        float hh = sh * 0.5f;
        const float invW = 1.0f / (float)W;
        const float invH = 1.0f / (float)H;

        int ok = b * TOPK + tid;
        out[ok * 4 + 0] = (xs - hw) * invW;
        out[ok * 4 + 1] = (ysv - hh) * invH;
        out[ok * 4 + 2] = (xs + hw) * invW;
        out[ok * 4 + 3] = (ysv + hh) * invH;
        out[BATCH * TOPK * 4 + ok] = p;                          // confi
        out[BATCH * TOPK * 4 + BATCH * TOPK + ok] = (float)c;    // classes
    }
}

extern "C" void kernel_launch(void* const* d_in, const int* in_sizes, int n_in,
                              void* d_out, int out_size) {
    const float* cls = (const float*)d_in[0];
    const float* dxy = (const float*)d_in[1];
    const float* swh = (const float*)d_in[2];
    float* out = (float*)d_out;

    zero_kernel<<<32, 1024>>>();
    peak_kernel<<<dim3(ROWLEN / 1024, H / YSTRIP, BATCH), 256>>>(cls);
    final_kernel<<<BATCH, 1024>>>(dxy, swh, out);
}

// round 6
// speedup vs baseline: 2.0165x; 1.0499x over previous
#include <cuda_runtime.h>
#include <cstdint>

#define BATCH   16
#define H       128
#define W       128
#define NC      80
#define ROWLEN  (W * NC)        // 10240
#define BATCHLEN (H * ROWLEN)   // 1310720
#define TOPK    100
#define NBINS   2048

// Scratch (device globals: allocation-free contract)
__device__ unsigned long long g_cand[BATCH][BATCHLEN];
__device__ unsigned int g_cnt[BATCH];
__device__ unsigned int g_hist[BATCH][NBINS];

// Identical sigmoid everywhere (monotone), so logit >= L0 ==> p >= sigmoid(L0).
__device__ __forceinline__ float sigmoidf_(float x) {
    return 1.0f / (1.0f + __expf(-x));
}

__global__ void zero_kernel() {
    unsigned i = blockIdx.x * blockDim.x + threadIdx.x;
    for (unsigned k = i; k < BATCH * NBINS; k += gridDim.x * blockDim.x)
        ((unsigned*)g_hist)[k] = 0u;
    if (i < BATCH) g_cnt[i] = 0u;
}

__device__ __forceinline__ float4 maxf4(float4 a, float4 b) {
    return make_float4(fmaxf(a.x, b.x), fmaxf(a.y, b.y),
                       fmaxf(a.z, b.z), fmaxf(a.w, b.w));
}

#define YSTRIP   32
#define NWARPS   8
#define WBUF     512            // per-warp staging capacity (keys)
#define WFLUSH   (WBUF - 128)   // max 128 appended per row

// Peak-NMS: logit-domain separable 3x3 max. Fully warp-autonomous appends:
// per-warp smem buffer, offsets from ballot popc arithmetic (no atomics, no
// shfl, no block barriers). Flush = 1 global atomic + coalesced warp copy.
__global__ __launch_bounds__(256) void peak_kernel(const float* __restrict__ cls) {
    __shared__ unsigned long long sbuf[NWARPS][WBUF];

    const int tid  = threadIdx.x;
    const int wid  = tid >> 5;
    const int lane = tid & 31;
    const unsigned lane_lt = (1u << lane) - 1u;

    const int b  = blockIdx.z;
    const int ys = blockIdx.y;
    const int j  = blockIdx.x * 1024 + tid * 4;   // column group within row
    const int xc = j / NC;                         // x coord (4 lanes share x)
    const bool hasL = (xc > 0);
    const bool hasR = (xc < W - 1);

    const float* base = cls + (size_t)b * BATCHLEN;
    const float NEG = __int_as_float(0xff800000);  // -inf
    const float4 NEG4 = make_float4(NEG, NEG, NEG, NEG);

    const int y0 = ys * YSTRIP;

    float4 hprev, hcur, vcur;
    if (y0 == 0) {
        hprev = NEG4;
    } else {
        const float* r = base + (y0 - 1) * ROWLEN + j;
        float4 Bv = *reinterpret_cast<const float4*>(r);
        float4 A = hasL ? *reinterpret_cast<const float4*>(r - NC) : NEG4;
        float4 C = hasR ? *reinterpret_cast<const float4*>(r + NC) : NEG4;
        hprev = maxf4(maxf4(A, Bv), C);
    }
    {
        const float* r = base + y0 * ROWLEN + j;
        float4 Bv = *reinterpret_cast<const float4*>(r);
        float4 A = hasL ? *reinterpret_cast<const float4*>(r - NC) : NEG4;
        float4 C = hasR ? *reinterpret_cast<const float4*>(r + NC) : NEG4;
        vcur = Bv;
        hcur = maxf4(maxf4(A, Bv), C);
    }

    unsigned wcnt = 0u;   // warp-uniform running count

    for (int y = y0; y < y0 + YSTRIP; ++y) {
        // flush if this row could overflow the warp buffer
        if (wcnt > (unsigned)WFLUSH) {
            __syncwarp();
            unsigned basep = 0u;
            if (lane == 0) basep = atomicAdd(&g_cnt[b], wcnt);
            basep = __shfl_sync(0xffffffffu, basep, 0);
            for (unsigned i = lane; i < wcnt; i += 32u)
                g_cand[b][basep + i] = sbuf[wid][i];
            wcnt = 0u;
        }

        float4 vnext, hnext;
        const int yn = y + 1;
        if (yn >= H) {
            vnext = NEG4; hnext = NEG4;
        } else {
            const float* r = base + yn * ROWLEN + j;
            float4 Bv = *reinterpret_cast<const float4*>(r);
            float4 A = hasL ? *reinterpret_cast<const float4*>(r - NC) : NEG4;
            float4 C = hasR ? *reinterpret_cast<const float4*>(r + NC) : NEG4;
            vnext = Bv;
            hnext = maxf4(maxf4(A, Bv), C);
        }

        float4 m = maxf4(maxf4(hprev, hcur), hnext);
        float vv[4] = {vcur.x, vcur.y, vcur.z, vcur.w};
        float mm[4] = {m.x, m.y, m.z, m.w};

        bool pk[4];
        unsigned ball[4];
        #pragma unroll
        for (int t = 0; t < 4; ++t) {
            pk[t] = (vv[t] == mm[t]);
            ball[t] = __ballot_sync(0xffffffffu, pk[t]);
        }

        unsigned rbase = wcnt;   // warp-uniform
        #pragma unroll
        for (int t = 0; t < 4; ++t) {
            if (pk[t]) {
                float v = vv[t];
                unsigned u = __float_as_uint(v);
                unsigned srt = ((int)u < 0) ? ~u : (u | 0x80000000u);
                atomicAdd(&g_hist[b][srt >> 21], 1u);   // RED.GLOBAL (no return)
                float p = sigmoidf_(v);
                unsigned idx = (unsigned)(y * ROWLEN + j + t);
                unsigned off = rbase + (unsigned)__popc(ball[t] & lane_lt);
                sbuf[wid][off] = ((unsigned long long)__float_as_uint(p) << 32)
                               | (unsigned long long)(0xFFFFFFFFu - idx);
            }
            rbase += (unsigned)__popc(ball[t]);   // warp-uniform
        }
        wcnt = rbase;

        hprev = hcur; hcur = hnext; vcur = vnext;
    }

    // final flush
    if (wcnt) {
        __syncwarp();
        unsigned basep = 0u;
        if (lane == 0) basep = atomicAdd(&g_cnt[b], wcnt);
        basep = __shfl_sync(0xffffffffu, basep, 0);
        for (unsigned i = lane; i < wcnt; i += 32u)
            g_cand[b][basep + i] = sbuf[wid][i];
    }
}

// Per-batch final: histogram walk -> p-domain threshold -> single collect scan
// -> bitonic sort of (p_bits<<32 | ~idx) keys (exact jax tie semantics) -> emit.
__global__ __launch_bounds__(1024) void final_kernel(const float* __restrict__ dxy,
                                                     const float* __restrict__ swh,
                                                     float* __restrict__ out) {
    const int b = blockIdx.x;
    const int tid = threadIdx.x;
    const int bd = blockDim.x;

    __shared__ unsigned int shist[NBINS];
    __shared__ unsigned long long list[4096];
    __shared__ unsigned int sh_thr;
    __shared__ unsigned int lcnt;

    unsigned N = g_cnt[b];
    if (N > (unsigned)BATCHLEN) N = BATCHLEN;
    const unsigned long long* cand = g_cand[b];

    for (int i = tid; i < NBINS; i += bd) shist[i] = g_hist[b][i];
    if (tid == 0) lcnt = 0u;
    __syncthreads();

    if (tid == 0) {
        unsigned thr = 0u;
        if (N > (unsigned)TOPK) {
            unsigned cum = 0u; int bt = 0;
            for (int i = NBINS - 1; i >= 0; --i) {
                cum += shist[i];
                if (cum >= (unsigned)TOPK) { bt = i; break; }
            }
            unsigned s = (unsigned)bt << 21;
            unsigned bits = (s & 0x80000000u) ? (s ^ 0x80000000u) : ~s;
            float L0 = __uint_as_float(bits);
            thr = __float_as_uint(sigmoidf_(L0));   // identical sigmoid
        }
        sh_thr = thr;
    }
    __syncthreads();
    const unsigned T = sh_thr;

    // single full pass over the candidate list
    for (unsigned i = tid; i < N; i += bd) {
        unsigned long long key = cand[i];
        if ((unsigned)(key >> 32) >= T) {
            unsigned p2 = atomicAdd(&lcnt, 1u);
            if (p2 < 4096u) list[p2] = key;
        }
    }
    __syncthreads();

    unsigned M = lcnt; if (M > 4096u) M = 4096u;
    unsigned P = 128u;
    while (P < M) P <<= 1;
    for (unsigned i = M + tid; i < P; i += bd) list[i] = 0ull;
    __syncthreads();

    // bitonic sort, descending (p desc, index asc on ties)
    for (unsigned k = 2u; k <= P; k <<= 1) {
        for (unsigned jj = k >> 1; jj > 0u; jj >>= 1) {
            for (unsigned i = tid; i < P; i += bd) {
                unsigned ixj = i ^ jj;
                if (ixj > i) {
                    unsigned long long a = list[i];
                    unsigned long long c = list[ixj];
                    bool up = ((i & k) == 0u);
                    bool sw = up ? (a < c) : (a > c);
                    if (sw) { list[i] = c; list[ixj] = a; }
                }
            }
            __syncthreads();
        }
    }

    if (tid < TOPK) {
        unsigned long long key = list[tid];
        float p = __uint_as_float((unsigned)(key >> 32));
        unsigned idx = 0xFFFFFFFFu - (unsigned)(key & 0xFFFFFFFFull);
        if (idx >= (unsigned)BATCHLEN) idx = 0u;   // only reachable via pad keys
        unsigned c = idx % NC;
        unsigned s = idx / NC;
        unsigned xg = s % W;
        unsigned yg = s / W;
        size_t gi = ((size_t)b * (H * W) + s) * 2;
        float dx = dxy[gi],  dy = dxy[gi + 1];
        float sw = swh[gi],  sh = swh[gi + 1];
        float xs = (float)xg + dx;
        float ysv = (float)yg + dy;
        float hw = sw * 0.5f;
        float hh = sh * 0.5f;
        const float invW = 1.0f / (float)W;
        const float invH = 1.0f / (float)H;

        int ok = b * TOPK + tid;
        out[ok * 4 + 0] = (xs - hw) * invW;
        out[ok * 4 + 1] = (ysv - hh) * invH;
        out[ok * 4 + 2] = (xs + hw) * invW;
        out[ok * 4 + 3] = (ysv + hh) * invH;
        out[BATCH * TOPK * 4 + ok] = p;                          // confi
        out[BATCH * TOPK * 4 + BATCH * TOPK + ok] = (float)c;    // classes
    }
}

extern "C" void kernel_launch(void* const* d_in, const int* in_sizes, int n_in,
                              void* d_out, int out_size) {
    const float* cls = (const float*)d_in[0];
    const float* dxy = (const float*)d_in[1];
    const float* swh = (const float*)d_in[2];
    float* out = (float*)d_out;

    zero_kernel<<<32, 1024>>>();
    peak_kernel<<<dim3(ROWLEN / 1024, H / YSTRIP, BATCH), 256>>>(cls);
    final_kernel<<<BATCH, 1024>>>(dxy, swh, out);
}